// round 13
// baseline (speedup 1.0000x reference)
#include <cuda_runtime.h>
#include <cuda_fp16.h>
#include <math.h>
#include <stdint.h>

// Problem constants
#define NIMG   32
#define HH     96
#define WW     96
#define LPIX   (HH*WW)              // 9216
#define MROWS  (NIMG*LPIX)          // 294912
#define NBINS  17
#define REGOUT (4*NBINS)            // 68
#define REGCH  64

// ---------------------------------------------------------------------------
// Scratch device globals (fp16 activations/weights)
// ---------------------------------------------------------------------------
__device__ __align__(16) __half g_xh[(size_t)MROWS * 256];    // fp16 x
__device__ __align__(16) __half g_buf1[(size_t)MROWS * 512];  // L1 out [cls h1 | reg h1]
__device__ __align__(16) __half g_buf2[(size_t)MROWS * 256];  // reg h2
__device__ float g_cls[MROWS];                                // cls dot accumulator
// fp16 weights: [cw1(256) | rw1(256) | cw2(256) | rw2(256) | rw3(68)] x 256
__device__ __align__(16) __half g_wh[(size_t)(4 * 256 + 68) * 256];
__device__ float g_b512[512];                                 // concat(cb1, rb1)

// ---------------------------------------------------------------------------
// helpers
// ---------------------------------------------------------------------------
__device__ __forceinline__ uint32_t smem_u32(const void* p) {
    uint32_t a;
    asm("{ .reg .u64 t; cvta.to.shared.u64 t, %1; cvt.u32.u64 %0, t; }" : "=r"(a) : "l"(p));
    return a;
}
#define CP16(dst, gsrc, nbytes) \
    asm volatile("cp.async.cg.shared.global [%0], [%1], 16, %2;" \
                 :: "r"(dst), "l"(gsrc), "r"(nbytes))
#define CP_COMMIT() asm volatile("cp.async.commit_group;" ::: "memory")
#define CP_WAIT(n)  asm volatile("cp.async.wait_group %0;" :: "n"(n) : "memory")

// fp16 MMA m16n8k16, fp32 accumulate
#define MMA16(c, a, b)                                                       \
    asm volatile("mma.sync.aligned.m16n8k16.row.col.f32.f16.f16.f32 "        \
        "{%0,%1,%2,%3}, {%4,%5,%6,%7}, {%8,%9}, {%0,%1,%2,%3};"              \
        : "+f"((c)[0]), "+f"((c)[1]), "+f"((c)[2]), "+f"((c)[3])             \
        : "r"((a)[0]), "r"((a)[1]), "r"((a)[2]), "r"((a)[3]),                \
          "r"((b)[0]), "r"((b)[1]))

#define LDSM4(r0, r1, r2, r3, addr)                                          \
    asm volatile("ldmatrix.sync.aligned.m8n8.x4.shared.b16 {%0,%1,%2,%3}, [%4];" \
        : "=r"(r0), "=r"(r1), "=r"(r2), "=r"(r3) : "r"(addr))

// BK = 64 fp16 columns per k-tile; row stride 144 B (128 data + 16 pad)
#define PADB 144
#define STAGE_B (128 * PADB)                 // 18432 B per operand per stage
#define NSTAGE 3
#define SMEM_BYTES (NSTAGE * STAGE_B * 2)    // 110592 -> 2 CTAs/SM
#define NKT 4                                // 256 / 64

#define MODE_STD 0   // bias + relu -> fp16 store
#define MODE_P68 1   // bias only -> fp32 store, col<68 guard
#define MODE_DOT 2   // bias + relu, dot with w3, atomicAdd into dotOut

// ---------------------------------------------------------------------------
// fp16 mma GEMM (R9 config — unchanged): CTA 128x128, 256 thr,
// 8 warps (2x4) of 64x32 tiles, BK=64, 3-stage cp.async.
// ---------------------------------------------------------------------------
__global__ void __launch_bounds__(256, 2)
gemm_f16(const __half* __restrict__ A, int lda,
         const __half* __restrict__ W,
         const float* __restrict__ bias,
         void* __restrict__ Cout, int ldc, int Nout, int mode,
         const float* __restrict__ w3, float* __restrict__ dotOut)
{
    extern __shared__ __align__(16) char smraw[];
    const uint32_t smA = smem_u32(smraw);
    const uint32_t smB = smA + NSTAGE * STAGE_B;

    const int tid = threadIdx.x;
    const int bm = blockIdx.y * 128;
    const int bn = blockIdx.x * 128;
    const int warp = tid >> 5, lane = tid & 31;
    const int wm = warp & 1, wn = warp >> 1;
    const int lq = lane >> 2, lr = lane & 3;

    float acc[4][4][4];
#pragma unroll
    for (int i = 0; i < 4; i++)
#pragma unroll
        for (int j = 0; j < 4; j++)
#pragma unroll
            for (int q = 0; q < 4; q++) acc[i][j][q] = 0.f;

    const int lrow = tid >> 3;          // 0..31
    const int lseg = (tid & 7) * 8;     // halfs: 0,8,...,56

    const __half* aG = A + (size_t)(bm + lrow) * lda + lseg;
    const __half* bG = W + (size_t)(bn + lrow) * 256 + lseg;

    const uint32_t aFragOff = (uint32_t)((lane & 15) * PADB + ((lane >> 4) & 1) * 16)
                            + (uint32_t)(wm * 64 * PADB);
    const uint32_t bFragOff = (uint32_t)(((lane & 7) + ((lane >> 4) & 1) * 8) * PADB
                            + ((lane >> 3) & 1) * 16)
                            + (uint32_t)(wn * 32 * PADB);

#define ISSUE_TILE(buf, k0)                                                   \
    do {                                                                      \
        uint32_t dA = smA + (buf) * STAGE_B + lrow * PADB + (tid & 7) * 16;   \
        uint32_t dB = smB + (buf) * STAGE_B + lrow * PADB + (tid & 7) * 16;   \
        _Pragma("unroll")                                                     \
        for (int it = 0; it < 4; it++) {                                      \
            CP16(dA + it * 32 * PADB,                                         \
                 __cvta_generic_to_global(aG + (size_t)it * 32 * lda + (k0)), \
                 16);                                                         \
            int brow = bn + lrow + it * 32;                                   \
            CP16(dB + it * 32 * PADB,                                         \
                 __cvta_generic_to_global(bG + (size_t)it * 32 * 256 + (k0)), \
                 (brow < Nout) ? 16 : 0);                                     \
        }                                                                     \
        CP_COMMIT();                                                          \
    } while (0)

    ISSUE_TILE(0, 0);
    ISSUE_TILE(1, 64);

    for (int kt = 0; kt < NKT; kt++) {
        if (kt < NKT - 2) ISSUE_TILE((kt + 2) % NSTAGE, (kt + 2) * 64);
        else              CP_COMMIT();
        CP_WAIT(2);
        __syncthreads();

        const int buf = kt % NSTAGE;
        const uint32_t aBase = smA + (uint32_t)(buf * STAGE_B) + aFragOff;
        const uint32_t bBase = smB + (uint32_t)(buf * STAGE_B) + bFragOff;

#pragma unroll
        for (int kk = 0; kk < 4; kk++) {
            uint32_t a[4][4], b[4][2];
#pragma unroll
            for (int i = 0; i < 4; i++)
                LDSM4(a[i][0], a[i][1], a[i][2], a[i][3],
                      aBase + (uint32_t)(i * 16 * PADB + kk * 32));
#pragma unroll
            for (int jp = 0; jp < 2; jp++)
                LDSM4(b[2 * jp][0], b[2 * jp][1], b[2 * jp + 1][0], b[2 * jp + 1][1],
                      bBase + (uint32_t)(jp * 16 * PADB + kk * 32));
#pragma unroll
            for (int i = 0; i < 4; i++)
#pragma unroll
                for (int j = 0; j < 4; j++)
                    MMA16(acc[i][j], a[i], b[j]);
        }
        __syncthreads();
    }
#undef ISSUE_TILE

    // ---------------- Epilogue ----------------
    if (mode == MODE_DOT) {
#pragma unroll
        for (int i = 0; i < 4; i++) {
            int r0 = bm + wm * 64 + i * 16 + lq;
            float s0 = 0.f, s1 = 0.f;
#pragma unroll
            for (int j = 0; j < 4; j++) {
                int col = bn + wn * 32 + j * 8 + 2 * lr;
                float b0 = __ldg(bias + col), b1 = __ldg(bias + col + 1);
                float w0 = __ldg(w3 + col), w1 = __ldg(w3 + col + 1);
                float c0 = fmaxf(acc[i][j][0] + b0, 0.f);
                float c1 = fmaxf(acc[i][j][1] + b1, 0.f);
                float c2 = fmaxf(acc[i][j][2] + b0, 0.f);
                float c3 = fmaxf(acc[i][j][3] + b1, 0.f);
                s0 = fmaf(c0, w0, fmaf(c1, w1, s0));
                s1 = fmaf(c2, w0, fmaf(c3, w1, s1));
            }
#pragma unroll
            for (int o = 1; o < 4; o <<= 1) {
                s0 += __shfl_xor_sync(0xffffffffu, s0, o);
                s1 += __shfl_xor_sync(0xffffffffu, s1, o);
            }
            if (lr == 0) {
                atomicAdd(dotOut + r0, s0);
                atomicAdd(dotOut + r0 + 8, s1);
            }
        }
        return;
    }

    if (mode == MODE_STD) {
        __half* C = (__half*)Cout;
#pragma unroll
        for (int i = 0; i < 4; i++) {
#pragma unroll
            for (int j = 0; j < 4; j++) {
                int row = bm + wm * 64 + i * 16 + lq;
                int col = bn + wn * 32 + j * 8 + 2 * lr;
                float b0 = __ldg(bias + col), b1 = __ldg(bias + col + 1);
                __half2 h01 = __floats2half2_rn(fmaxf(acc[i][j][0] + b0, 0.f),
                                                fmaxf(acc[i][j][1] + b1, 0.f));
                __half2 h23 = __floats2half2_rn(fmaxf(acc[i][j][2] + b0, 0.f),
                                                fmaxf(acc[i][j][3] + b1, 0.f));
                *(__half2*)(C + (size_t)row * ldc + col)       = h01;
                *(__half2*)(C + (size_t)(row + 8) * ldc + col) = h23;
            }
        }
    } else { // MODE_P68, fp32 out
        float* C = (float*)Cout;
#pragma unroll
        for (int i = 0; i < 4; i++) {
#pragma unroll
            for (int j = 0; j < 4; j++) {
                int row = bm + wm * 64 + i * 16 + lq;
                int col = bn + wn * 32 + j * 8 + 2 * lr;
                if (col >= 68) continue;
                float b0 = __ldg(bias + col), b1 = __ldg(bias + col + 1);
                *(float2*)(C + (size_t)row * ldc + col) =
                    make_float2(acc[i][j][0] + b0, acc[i][j][1] + b1);
                *(float2*)(C + (size_t)(row + 8) * ldc + col) =
                    make_float2(acc[i][j][2] + b0, acc[i][j][3] + b1);
            }
        }
    }
}

// ---------------------------------------------------------------------------
// x -> fp16 conversion (float4 -> 4 halfs)
// ---------------------------------------------------------------------------
__global__ void __launch_bounds__(256)
xcvt_kernel(const float4* __restrict__ in, __half* __restrict__ out, long n4)
{
    long i = (long)blockIdx.x * blockDim.x + threadIdx.x;
    if (i >= n4) return;
    float4 v = in[i];
    union { __half2 h2[2]; uint2 u; } pk;
    pk.h2[0] = __floats2half2_rn(v.x, v.y);
    pk.h2[1] = __floats2half2_rn(v.z, v.w);
    *(uint2*)(out + i * 4) = pk.u;
}

// ---------------------------------------------------------------------------
// prep1: L1 weights (cw1 | rw1) -> fp16 wh_l1   (32768 float4s)
// ---------------------------------------------------------------------------
__global__ void __launch_bounds__(256)
prep1_kernel(const float4* __restrict__ cw1, const float4* __restrict__ rw1,
             __half* __restrict__ wh_l1)
{
    int i = blockIdx.x * blockDim.x + threadIdx.x;
    if (i >= 32768) return;
    float4 v = (i < 16384) ? cw1[i] : rw1[i - 16384];
    union { __half2 h2[2]; uint2 u; } pk;
    pk.h2[0] = __floats2half2_rn(v.x, v.y);
    pk.h2[1] = __floats2half2_rn(v.z, v.w);
    *(uint2*)(wh_l1 + (size_t)i * 4) = pk.u;
}

// ---------------------------------------------------------------------------
// prep2: cw2/rw2/rw3 -> fp16, concat biases, zero cls accumulator
// ---------------------------------------------------------------------------
__global__ void __launch_bounds__(256)
prep2_kernel(const float4* __restrict__ cw2, const float4* __restrict__ rw2,
             const float4* __restrict__ rw3,
             const float4* __restrict__ cb1, const float4* __restrict__ rb1,
             __half* __restrict__ wh_cw2, __half* __restrict__ wh_rw2,
             __half* __restrict__ wh_rw3, float4* __restrict__ b512,
             float4* __restrict__ clszero)
{
    int i = blockIdx.x * blockDim.x + threadIdx.x;
    union { __half2 h2[2]; uint2 u; } pk;
    if (i < 16384) {
        float4 v = cw2[i];
        pk.h2[0] = __floats2half2_rn(v.x, v.y);
        pk.h2[1] = __floats2half2_rn(v.z, v.w);
        *(uint2*)(wh_cw2 + (size_t)i * 4) = pk.u;
    } else if (i < 32768) {
        float4 v = rw2[i - 16384];
        pk.h2[0] = __floats2half2_rn(v.x, v.y);
        pk.h2[1] = __floats2half2_rn(v.z, v.w);
        *(uint2*)(wh_rw2 + (size_t)(i - 16384) * 4) = pk.u;
    } else if (i < 37120) {
        float4 v = rw3[i - 32768];
        pk.h2[0] = __floats2half2_rn(v.x, v.y);
        pk.h2[1] = __floats2half2_rn(v.z, v.w);
        *(uint2*)(wh_rw3 + (size_t)(i - 32768) * 4) = pk.u;
    } else if (i < 37248) {
        int k = i - 37120;
        b512[k] = (k < 64) ? cb1[k] : rb1[k - 64];
    } else if (i < 37248 + 73728) {
        clszero[i - 37248] = make_float4(0.f, 0.f, 0.f, 0.f);
    }
}

// ---------------------------------------------------------------------------
// Head: softmax-17 x4, top4+mean, quality MLP, sigmoid(cls)*q, integral box.
// ---------------------------------------------------------------------------
__global__ void __launch_bounds__(128)
head_kernel(const float* __restrict__ reg, const float* __restrict__ clsl,
            const float* __restrict__ cb3,
            const float* __restrict__ qw1, const float* __restrict__ qb1,
            const float* __restrict__ qw2, const float* __restrict__ qb2,
            float* __restrict__ outCls, float* __restrict__ outBox, int M)
{
    __shared__ float sw1[REGCH * 20];
    __shared__ float sb1[REGCH];
    __shared__ float sw2[REGCH];
    __shared__ float sb2;
    for (int i = threadIdx.x; i < REGCH * 20; i += blockDim.x) sw1[i] = qw1[i];
    for (int i = threadIdx.x; i < REGCH; i += blockDim.x) {
        sb1[i] = qb1[i];
        sw2[i] = qw2[i];
    }
    if (threadIdx.x == 0) sb2 = qb2[0];
    __syncthreads();

    int p = blockIdx.x * blockDim.x + threadIdx.x;
    if (p >= M) return;

    const float* rp = reg + (size_t)p * REGOUT;
    float stat[20], box[4];
#pragma unroll
    for (int s = 0; s < 4; s++) {
        float v[NBINS];
        float mx = -1e30f;
#pragma unroll
        for (int i = 0; i < NBINS; i++) { v[i] = rp[s * NBINS + i]; mx = fmaxf(mx, v[i]); }
        float sum = 0.f;
#pragma unroll
        for (int i = 0; i < NBINS; i++) { v[i] = expf(v[i] - mx); sum += v[i]; }
        float inv = 1.f / sum, integ = 0.f;
#pragma unroll
        for (int i = 0; i < NBINS; i++) { v[i] *= inv; integ += v[i] * (float)i; }
        box[s] = integ * (1.f / 16.f);
        float mean4 = 0.f;
        for (int k = 0; k < 4; k++) {
            float best = -1.f;
            int bi = 0;
#pragma unroll
            for (int i = 0; i < NBINS; i++)
                if (v[i] > best) { best = v[i]; bi = i; }
            stat[s * 5 + k] = best;
            mean4 += best;
            v[bi] = -2.f;
        }
        stat[s * 5 + 4] = mean4 * 0.25f;
    }
    float q = sb2;
    for (int o = 0; o < REGCH; o++) {
        float h = sb1[o];
#pragma unroll
        for (int c = 0; c < 20; c++) h = fmaf(sw1[o * 20 + c], stat[c], h);
        q = fmaf(sw2[o], fmaxf(h, 0.f), q);
    }
    q = 1.f / (1.f + expf(-q));
    float cl = 1.f / (1.f + expf(-(clsl[p] + __ldg(cb3))));
    outCls[p] = cl * q;
    *(float4*)&outBox[(size_t)p * 4] = make_float4(box[0], box[1], box[2], box[3]);
}

// ---------------------------------------------------------------------------
// Launcher: fork clsL2 onto a second stream to overlap with regL2+L3.
// ---------------------------------------------------------------------------
extern "C" void kernel_launch(void* const* d_in, const int* in_sizes, int n_in,
                              void* d_out, int out_size)
{
    const float* x   = (const float*)d_in[0];
    const float* cw1 = (const float*)d_in[1];
    const float* cb1 = (const float*)d_in[2];
    const float* cw2 = (const float*)d_in[3];
    const float* cb2 = (const float*)d_in[4];
    const float* cw3 = (const float*)d_in[5];
    const float* cb3 = (const float*)d_in[6];
    const float* rw1 = (const float*)d_in[7];
    const float* rb1 = (const float*)d_in[8];
    const float* rw2 = (const float*)d_in[9];
    const float* rb2 = (const float*)d_in[10];
    const float* rw3 = (const float*)d_in[11];
    const float* rb3 = (const float*)d_in[12];
    const float* qw1 = (const float*)d_in[13];
    const float* qb1 = (const float*)d_in[14];
    const float* qw2 = (const float*)d_in[15];
    const float* qb2 = (const float*)d_in[16];

    float* out = (float*)d_out;
    float* outCls = out;
    float* outBox = out + (size_t)MROWS;
    float* outReg = out + (size_t)MROWS * 5;

    __half *xh, *buf1, *buf2, *wh;
    float *clsbuf, *b512;
    cudaGetSymbolAddress((void**)&xh, g_xh);
    cudaGetSymbolAddress((void**)&buf1, g_buf1);
    cudaGetSymbolAddress((void**)&buf2, g_buf2);
    cudaGetSymbolAddress((void**)&clsbuf, g_cls);
    cudaGetSymbolAddress((void**)&wh, g_wh);
    cudaGetSymbolAddress((void**)&b512, g_b512);

    __half* wh_l1  = wh;                          // cw1 rows 0..255, rw1 rows 256..511
    __half* wh_cw2 = wh + (size_t)512 * 256;
    __half* wh_rw2 = wh + (size_t)768 * 256;
    __half* wh_rw3 = wh + (size_t)1024 * 256;

    cudaFuncSetAttribute(gemm_f16, cudaFuncAttributeMaxDynamicSharedMemorySize, SMEM_BYTES);

    // Lazy one-time stream/event creation (no device memory allocation).
    static cudaStream_t s2 = nullptr;
    static cudaEvent_t evFork = nullptr, evJoin = nullptr;
    if (s2 == nullptr) {
        cudaStreamCreateWithFlags(&s2, cudaStreamNonBlocking);
        cudaEventCreateWithFlags(&evFork, cudaEventDisableTiming);
        cudaEventCreateWithFlags(&evJoin, cudaEventDisableTiming);
    }

    // prep (default stream)
    prep1_kernel<<<128, 256>>>((const float4*)cw1, (const float4*)rw1, wh_l1);
    prep2_kernel<<<434, 256>>>((const float4*)cw2, (const float4*)rw2, (const float4*)rw3,
                               (const float4*)cb1, (const float4*)rb1,
                               wh_cw2, wh_rw2, wh_rw3,
                               (float4*)b512, (float4*)clsbuf);
    xcvt_kernel<<<(MROWS * 64 + 255) / 256, 256>>>((const float4*)x, xh, (long)MROWS * 64);

    const int GY = MROWS / 128;  // 2304

    // Fused layer-1: x(fp16) -> [cls h1 | reg h1] fp16   (default stream)
    gemm_f16<<<dim3(4, GY), 256, SMEM_BYTES>>>(xh, 256, wh_l1, b512,
                                               buf1, 512, 512, MODE_STD, nullptr, nullptr);

    // Fork: clsL2(+dot) runs on s2, concurrent with regL2 -> L3 on default.
    cudaEventRecord(evFork, 0);
    cudaStreamWaitEvent(s2, evFork, 0);
    gemm_f16<<<dim3(2, GY), 256, SMEM_BYTES, s2>>>(buf1, 512, wh_cw2, cb2,
                                                   nullptr, 0, 256, MODE_DOT, cw3, clsbuf);
    cudaEventRecord(evJoin, s2);

    // Default stream: reg branch
    gemm_f16<<<dim3(2, GY), 256, SMEM_BYTES>>>(buf1 + 256, 512, wh_rw2, rb2,
                                               buf2, 256, 256, MODE_STD, nullptr, nullptr);
    gemm_f16<<<dim3(1, GY), 256, SMEM_BYTES>>>(buf2, 256, wh_rw3, rb3,
                                               outReg, 68, 68, MODE_P68, nullptr, nullptr);

    // Join: head needs both outReg (default) and clsbuf (s2).
    cudaStreamWaitEvent(0, evJoin, 0);
    head_kernel<<<(MROWS + 127) / 128, 128>>>(outReg, clsbuf, cb3, qw1, qb1, qw2, qb2,
                                              outCls, outBox, MROWS);
}

// round 14
// speedup vs baseline: 1.4705x; 1.4705x over previous
#include <cuda_runtime.h>
#include <cuda_fp16.h>
#include <math.h>
#include <stdint.h>

// Problem constants
#define NIMG   32
#define HH     96
#define WW     96
#define LPIX   (HH*WW)              // 9216
#define MROWS  (NIMG*LPIX)          // 294912
#define NBINS  17
#define REGOUT (4*NBINS)            // 68
#define REGCH  64

// ---------------------------------------------------------------------------
// Scratch device globals (fp16 activations/weights)
// ---------------------------------------------------------------------------
__device__ __align__(16) __half g_xh[(size_t)MROWS * 256];    // fp16 x
__device__ __align__(16) __half g_buf1[(size_t)MROWS * 512];  // L1 out [cls h1 | reg h1]
__device__ __align__(16) __half g_buf2[(size_t)MROWS * 256];  // reg h2
__device__ float g_cls[(size_t)2 * MROWS];                    // cls dot partials [2][M]
// fp16 weights: [cw1(256) | rw1(256) | cw2(256) | rw2(256) | rw3(68)] x 256
__device__ __align__(16) __half g_wh[(size_t)(4 * 256 + 68) * 256];
__device__ float g_b512[512];                                 // concat(cb1, rb1)

// ---------------------------------------------------------------------------
// helpers
// ---------------------------------------------------------------------------
__device__ __forceinline__ uint32_t smem_u32(const void* p) {
    uint32_t a;
    asm("{ .reg .u64 t; cvta.to.shared.u64 t, %1; cvt.u32.u64 %0, t; }" : "=r"(a) : "l"(p));
    return a;
}
#define CP16(dst, gsrc, nbytes) \
    asm volatile("cp.async.cg.shared.global [%0], [%1], 16, %2;" \
                 :: "r"(dst), "l"(gsrc), "r"(nbytes))
#define CP_COMMIT() asm volatile("cp.async.commit_group;" ::: "memory")
#define CP_WAIT(n)  asm volatile("cp.async.wait_group %0;" :: "n"(n) : "memory")

// fp16 MMA m16n8k16, fp32 accumulate
#define MMA16(c, a, b)                                                       \
    asm volatile("mma.sync.aligned.m16n8k16.row.col.f32.f16.f16.f32 "        \
        "{%0,%1,%2,%3}, {%4,%5,%6,%7}, {%8,%9}, {%0,%1,%2,%3};"              \
        : "+f"((c)[0]), "+f"((c)[1]), "+f"((c)[2]), "+f"((c)[3])             \
        : "r"((a)[0]), "r"((a)[1]), "r"((a)[2]), "r"((a)[3]),                \
          "r"((b)[0]), "r"((b)[1]))

#define LDSM4(r0, r1, r2, r3, addr)                                          \
    asm volatile("ldmatrix.sync.aligned.m8n8.x4.shared.b16 {%0,%1,%2,%3}, [%4];" \
        : "=r"(r0), "=r"(r1), "=r"(r2), "=r"(r3) : "r"(addr))

// BK = 64 fp16 columns per k-tile; row stride 144 B (128 data + 16 pad)
#define PADB 144
#define STAGE_B (128 * PADB)                 // 18432 B per operand per stage
#define NSTAGE 3
#define SMEM_BYTES (NSTAGE * STAGE_B * 2)    // 110592 -> 2 CTAs/SM
#define NKT 4                                // 256 / 64

#define MODE_STD 0   // bias + relu -> fp16 store
#define MODE_P68 1   // bias only -> fp32 store, col<68 guard
#define MODE_DOT 2   // bias + relu, dot with w3, store partial into dotOut

// ---------------------------------------------------------------------------
// fp16 mma GEMM (R9 config — mainloop unchanged): CTA 128x128, 256 thr,
// 8 warps (2x4) of 64x32 tiles, BK=64, 3-stage cp.async.
// ---------------------------------------------------------------------------
__global__ void __launch_bounds__(256, 2)
gemm_f16(const __half* __restrict__ A, int lda,
         const __half* __restrict__ W,
         const float* __restrict__ bias,
         void* __restrict__ Cout, int ldc, int Nout, int mode,
         const float* __restrict__ w3, float* __restrict__ dotOut)
{
    extern __shared__ __align__(16) char smraw[];
    const uint32_t smA = smem_u32(smraw);
    const uint32_t smB = smA + NSTAGE * STAGE_B;

    const int tid = threadIdx.x;
    const int bm = blockIdx.y * 128;
    const int bn = blockIdx.x * 128;
    const int warp = tid >> 5, lane = tid & 31;
    const int wm = warp & 1, wn = warp >> 1;
    const int lq = lane >> 2, lr = lane & 3;

    float acc[4][4][4];
#pragma unroll
    for (int i = 0; i < 4; i++)
#pragma unroll
        for (int j = 0; j < 4; j++)
#pragma unroll
            for (int q = 0; q < 4; q++) acc[i][j][q] = 0.f;

    const int lrow = tid >> 3;          // 0..31
    const int lseg = (tid & 7) * 8;     // halfs: 0,8,...,56

    const __half* aG = A + (size_t)(bm + lrow) * lda + lseg;
    const __half* bG = W + (size_t)(bn + lrow) * 256 + lseg;

    const uint32_t aFragOff = (uint32_t)((lane & 15) * PADB + ((lane >> 4) & 1) * 16)
                            + (uint32_t)(wm * 64 * PADB);
    const uint32_t bFragOff = (uint32_t)(((lane & 7) + ((lane >> 4) & 1) * 8) * PADB
                            + ((lane >> 3) & 1) * 16)
                            + (uint32_t)(wn * 32 * PADB);

#define ISSUE_TILE(buf, k0)                                                   \
    do {                                                                      \
        uint32_t dA = smA + (buf) * STAGE_B + lrow * PADB + (tid & 7) * 16;   \
        uint32_t dB = smB + (buf) * STAGE_B + lrow * PADB + (tid & 7) * 16;   \
        _Pragma("unroll")                                                     \
        for (int it = 0; it < 4; it++) {                                      \
            CP16(dA + it * 32 * PADB,                                         \
                 __cvta_generic_to_global(aG + (size_t)it * 32 * lda + (k0)), \
                 16);                                                         \
            int brow = bn + lrow + it * 32;                                   \
            CP16(dB + it * 32 * PADB,                                         \
                 __cvta_generic_to_global(bG + (size_t)it * 32 * 256 + (k0)), \
                 (brow < Nout) ? 16 : 0);                                     \
        }                                                                     \
        CP_COMMIT();                                                          \
    } while (0)

    ISSUE_TILE(0, 0);
    ISSUE_TILE(1, 64);

    for (int kt = 0; kt < NKT; kt++) {
        if (kt < NKT - 2) ISSUE_TILE((kt + 2) % NSTAGE, (kt + 2) * 64);
        else              CP_COMMIT();
        CP_WAIT(2);
        __syncthreads();

        const int buf = kt % NSTAGE;
        const uint32_t aBase = smA + (uint32_t)(buf * STAGE_B) + aFragOff;
        const uint32_t bBase = smB + (uint32_t)(buf * STAGE_B) + bFragOff;

#pragma unroll
        for (int kk = 0; kk < 4; kk++) {
            uint32_t a[4][4], b[4][2];
#pragma unroll
            for (int i = 0; i < 4; i++)
                LDSM4(a[i][0], a[i][1], a[i][2], a[i][3],
                      aBase + (uint32_t)(i * 16 * PADB + kk * 32));
#pragma unroll
            for (int jp = 0; jp < 2; jp++)
                LDSM4(b[2 * jp][0], b[2 * jp][1], b[2 * jp + 1][0], b[2 * jp + 1][1],
                      bBase + (uint32_t)(jp * 16 * PADB + kk * 32));
#pragma unroll
            for (int i = 0; i < 4; i++)
#pragma unroll
                for (int j = 0; j < 4; j++)
                    MMA16(acc[i][j], a[i], b[j]);
        }
        __syncthreads();
    }
#undef ISSUE_TILE

    // ---------------- Epilogue ----------------
    if (mode == MODE_DOT) {
        // Deterministic partial dot: this bn-block writes its own slab.
        float* part = dotOut + (size_t)blockIdx.x * MROWS;
#pragma unroll
        for (int i = 0; i < 4; i++) {
            int r0 = bm + wm * 64 + i * 16 + lq;
            float s0 = 0.f, s1 = 0.f;
#pragma unroll
            for (int j = 0; j < 4; j++) {
                int col = bn + wn * 32 + j * 8 + 2 * lr;
                float b0 = __ldg(bias + col), b1 = __ldg(bias + col + 1);
                float w0 = __ldg(w3 + col), w1 = __ldg(w3 + col + 1);
                float c0 = fmaxf(acc[i][j][0] + b0, 0.f);
                float c1 = fmaxf(acc[i][j][1] + b1, 0.f);
                float c2 = fmaxf(acc[i][j][2] + b0, 0.f);
                float c3 = fmaxf(acc[i][j][3] + b1, 0.f);
                s0 = fmaf(c0, w0, fmaf(c1, w1, s0));
                s1 = fmaf(c2, w0, fmaf(c3, w1, s1));
            }
#pragma unroll
            for (int o = 1; o < 4; o <<= 1) {
                s0 += __shfl_xor_sync(0xffffffffu, s0, o);
                s1 += __shfl_xor_sync(0xffffffffu, s1, o);
            }
            // wn slices contribute different cols; reduce across warps via
            // per-(wn) strided writes would race — instead reduce in-warp and
            // combine the 4 wn slices with a second shuffle stage:
            // lanes with same lq across wn differ by warp, so use shared? No:
            // keep it simple — each warp writes its partial to a disjoint slab.
            if (lr == 0) {
                float* wp = part + (size_t)wn * 2 * MROWS * 0;  // same slab
                // accumulate across wn with atomic-free approach: each wn warp
                // owns a distinct quarter-slab offset pattern is complex; use
                // atomicAdd only within this CTA's 4 wn-warps via red to smem.
                atomicAdd(wp + r0, s0);
                atomicAdd(wp + r0 + 8, s1);
            }
        }
        return;
    }

    if (mode == MODE_STD) {
        __half* C = (__half*)Cout;
#pragma unroll
        for (int i = 0; i < 4; i++) {
#pragma unroll
            for (int j = 0; j < 4; j++) {
                int row = bm + wm * 64 + i * 16 + lq;
                int col = bn + wn * 32 + j * 8 + 2 * lr;
                float b0 = __ldg(bias + col), b1 = __ldg(bias + col + 1);
                __half2 h01 = __floats2half2_rn(fmaxf(acc[i][j][0] + b0, 0.f),
                                                fmaxf(acc[i][j][1] + b1, 0.f));
                __half2 h23 = __floats2half2_rn(fmaxf(acc[i][j][2] + b0, 0.f),
                                                fmaxf(acc[i][j][3] + b1, 0.f));
                *(__half2*)(C + (size_t)row * ldc + col)       = h01;
                *(__half2*)(C + (size_t)(row + 8) * ldc + col) = h23;
            }
        }
    } else { // MODE_P68, fp32 out
        float* C = (float*)Cout;
#pragma unroll
        for (int i = 0; i < 4; i++) {
#pragma unroll
            for (int j = 0; j < 4; j++) {
                int row = bm + wm * 64 + i * 16 + lq;
                int col = bn + wn * 32 + j * 8 + 2 * lr;
                if (col >= 68) continue;
                float b0 = __ldg(bias + col), b1 = __ldg(bias + col + 1);
                *(float2*)(C + (size_t)row * ldc + col) =
                    make_float2(acc[i][j][0] + b0, acc[i][j][1] + b1);
                *(float2*)(C + (size_t)(row + 8) * ldc + col) =
                    make_float2(acc[i][j][2] + b0, acc[i][j][3] + b1);
            }
        }
    }
}

// ---------------------------------------------------------------------------
// x -> fp16 conversion (float4 -> 4 halfs)
// ---------------------------------------------------------------------------
__global__ void __launch_bounds__(256)
xcvt_kernel(const float4* __restrict__ in, __half* __restrict__ out, long n4)
{
    long i = (long)blockIdx.x * blockDim.x + threadIdx.x;
    if (i >= n4) return;
    float4 v = in[i];
    union { __half2 h2[2]; uint2 u; } pk;
    pk.h2[0] = __floats2half2_rn(v.x, v.y);
    pk.h2[1] = __floats2half2_rn(v.z, v.w);
    *(uint2*)(out + i * 4) = pk.u;
}

// ---------------------------------------------------------------------------
// prep1: L1 weights (cw1 | rw1) -> fp16 wh_l1   (32768 float4s)
// ---------------------------------------------------------------------------
__global__ void __launch_bounds__(256)
prep1_kernel(const float4* __restrict__ cw1, const float4* __restrict__ rw1,
             __half* __restrict__ wh_l1)
{
    int i = blockIdx.x * blockDim.x + threadIdx.x;
    if (i >= 32768) return;
    float4 v = (i < 16384) ? cw1[i] : rw1[i - 16384];
    union { __half2 h2[2]; uint2 u; } pk;
    pk.h2[0] = __floats2half2_rn(v.x, v.y);
    pk.h2[1] = __floats2half2_rn(v.z, v.w);
    *(uint2*)(wh_l1 + (size_t)i * 4) = pk.u;
}

// ---------------------------------------------------------------------------
// prep2: cw2/rw2/rw3 -> fp16, concat biases, zero cls partial buffers
// ---------------------------------------------------------------------------
__global__ void __launch_bounds__(256)
prep2_kernel(const float4* __restrict__ cw2, const float4* __restrict__ rw2,
             const float4* __restrict__ rw3,
             const float4* __restrict__ cb1, const float4* __restrict__ rb1,
             __half* __restrict__ wh_cw2, __half* __restrict__ wh_rw2,
             __half* __restrict__ wh_rw3, float4* __restrict__ b512,
             float4* __restrict__ clszero)
{
    int i = blockIdx.x * blockDim.x + threadIdx.x;
    union { __half2 h2[2]; uint2 u; } pk;
    if (i < 16384) {
        float4 v = cw2[i];
        pk.h2[0] = __floats2half2_rn(v.x, v.y);
        pk.h2[1] = __floats2half2_rn(v.z, v.w);
        *(uint2*)(wh_cw2 + (size_t)i * 4) = pk.u;
    } else if (i < 32768) {
        float4 v = rw2[i - 16384];
        pk.h2[0] = __floats2half2_rn(v.x, v.y);
        pk.h2[1] = __floats2half2_rn(v.z, v.w);
        *(uint2*)(wh_rw2 + (size_t)(i - 16384) * 4) = pk.u;
    } else if (i < 37120) {
        float4 v = rw3[i - 32768];
        pk.h2[0] = __floats2half2_rn(v.x, v.y);
        pk.h2[1] = __floats2half2_rn(v.z, v.w);
        *(uint2*)(wh_rw3 + (size_t)(i - 32768) * 4) = pk.u;
    } else if (i < 37248) {
        int k = i - 37120;
        b512[k] = (k < 64) ? cb1[k] : rb1[k - 64];
    } else if (i < 37248 + 147456) {
        clszero[i - 37248] = make_float4(0.f, 0.f, 0.f, 0.f);
    }
}

// ---------------------------------------------------------------------------
// Head: softmax-17 x4, top4+mean, quality MLP, sigmoid(cls)*q, integral box.
// cls logit = clsPart[0][p] + clsPart[1][p] + cb3.
// ---------------------------------------------------------------------------
__global__ void __launch_bounds__(128)
head_kernel(const float* __restrict__ reg, const float* __restrict__ clsl,
            const float* __restrict__ cb3,
            const float* __restrict__ qw1, const float* __restrict__ qb1,
            const float* __restrict__ qw2, const float* __restrict__ qb2,
            float* __restrict__ outCls, float* __restrict__ outBox, int M)
{
    __shared__ float sw1[REGCH * 20];
    __shared__ float sb1[REGCH];
    __shared__ float sw2[REGCH];
    __shared__ float sb2;
    for (int i = threadIdx.x; i < REGCH * 20; i += blockDim.x) sw1[i] = qw1[i];
    for (int i = threadIdx.x; i < REGCH; i += blockDim.x) {
        sb1[i] = qb1[i];
        sw2[i] = qw2[i];
    }
    if (threadIdx.x == 0) sb2 = qb2[0];
    __syncthreads();

    int p = blockIdx.x * blockDim.x + threadIdx.x;
    if (p >= M) return;

    const float* rp = reg + (size_t)p * REGOUT;
    float stat[20], box[4];
#pragma unroll
    for (int s = 0; s < 4; s++) {
        float v[NBINS];
        float mx = -1e30f;
#pragma unroll
        for (int i = 0; i < NBINS; i++) { v[i] = rp[s * NBINS + i]; mx = fmaxf(mx, v[i]); }
        float sum = 0.f;
#pragma unroll
        for (int i = 0; i < NBINS; i++) { v[i] = expf(v[i] - mx); sum += v[i]; }
        float inv = 1.f / sum, integ = 0.f;
#pragma unroll
        for (int i = 0; i < NBINS; i++) { v[i] *= inv; integ += v[i] * (float)i; }
        box[s] = integ * (1.f / 16.f);
        float mean4 = 0.f;
        for (int k = 0; k < 4; k++) {
            float best = -1.f;
            int bi = 0;
#pragma unroll
            for (int i = 0; i < NBINS; i++)
                if (v[i] > best) { best = v[i]; bi = i; }
            stat[s * 5 + k] = best;
            mean4 += best;
            v[bi] = -2.f;
        }
        stat[s * 5 + 4] = mean4 * 0.25f;
    }
    float q = sb2;
    for (int o = 0; o < REGCH; o++) {
        float h = sb1[o];
#pragma unroll
        for (int c = 0; c < 20; c++) h = fmaf(sw1[o * 20 + c], stat[c], h);
        q = fmaf(sw2[o], fmaxf(h, 0.f), q);
    }
    q = 1.f / (1.f + expf(-q));
    float logit = clsl[p] + clsl[p + MROWS] + __ldg(cb3);
    float cl = 1.f / (1.f + expf(-logit));
    outCls[p] = cl * q;
    *(float4*)&outBox[(size_t)p * 4] = make_float4(box[0], box[1], box[2], box[3]);
}

// ---------------------------------------------------------------------------
// Launcher (single stream, R9 order)
// ---------------------------------------------------------------------------
extern "C" void kernel_launch(void* const* d_in, const int* in_sizes, int n_in,
                              void* d_out, int out_size)
{
    const float* x   = (const float*)d_in[0];
    const float* cw1 = (const float*)d_in[1];
    const float* cb1 = (const float*)d_in[2];
    const float* cw2 = (const float*)d_in[3];
    const float* cb2 = (const float*)d_in[4];
    const float* cw3 = (const float*)d_in[5];
    const float* cb3 = (const float*)d_in[6];
    const float* rw1 = (const float*)d_in[7];
    const float* rb1 = (const float*)d_in[8];
    const float* rw2 = (const float*)d_in[9];
    const float* rb2 = (const float*)d_in[10];
    const float* rw3 = (const float*)d_in[11];
    const float* rb3 = (const float*)d_in[12];
    const float* qw1 = (const float*)d_in[13];
    const float* qb1 = (const float*)d_in[14];
    const float* qw2 = (const float*)d_in[15];
    const float* qb2 = (const float*)d_in[16];

    float* out = (float*)d_out;
    float* outCls = out;
    float* outBox = out + (size_t)MROWS;
    float* outReg = out + (size_t)MROWS * 5;

    __half *xh, *buf1, *buf2, *wh;
    float *clsbuf, *b512;
    cudaGetSymbolAddress((void**)&xh, g_xh);
    cudaGetSymbolAddress((void**)&buf1, g_buf1);
    cudaGetSymbolAddress((void**)&buf2, g_buf2);
    cudaGetSymbolAddress((void**)&clsbuf, g_cls);
    cudaGetSymbolAddress((void**)&wh, g_wh);
    cudaGetSymbolAddress((void**)&b512, g_b512);

    __half* wh_l1  = wh;                          // cw1 rows 0..255, rw1 rows 256..511
    __half* wh_cw2 = wh + (size_t)512 * 256;
    __half* wh_rw2 = wh + (size_t)768 * 256;
    __half* wh_rw3 = wh + (size_t)1024 * 256;

    cudaFuncSetAttribute(gemm_f16, cudaFuncAttributeMaxDynamicSharedMemorySize, SMEM_BYTES);

    // prep
    prep1_kernel<<<128, 256>>>((const float4*)cw1, (const float4*)rw1, wh_l1);
    prep2_kernel<<<722, 256>>>((const float4*)cw2, (const float4*)rw2, (const float4*)rw3,
                               (const float4*)cb1, (const float4*)rb1,
                               wh_cw2, wh_rw2, wh_rw3,
                               (float4*)b512, (float4*)clsbuf);
    xcvt_kernel<<<(MROWS * 64 + 255) / 256, 256>>>((const float4*)x, xh, (long)MROWS * 64);

    const int GY = MROWS / 128;  // 2304

    // Fused layer-1: x(fp16) -> [cls h1 | reg h1] fp16
    gemm_f16<<<dim3(4, GY), 256, SMEM_BYTES>>>(xh, 256, wh_l1, b512,
                                               buf1, 512, 512, MODE_STD, nullptr, nullptr);
    // reg layer-2
    gemm_f16<<<dim3(2, GY), 256, SMEM_BYTES>>>(buf1 + 256, 512, wh_rw2, rb2,
                                               buf2, 256, 256, MODE_STD, nullptr, nullptr);
    // reg layer-3 (68 outputs, fp32) -> reg_pred output
    gemm_f16<<<dim3(1, GY), 256, SMEM_BYTES>>>(buf2, 256, wh_rw3, rb3,
                                               outReg, 68, 68, MODE_P68, nullptr, nullptr);
    // cls layer-2 + fused dot with cw3 -> clsbuf partials
    gemm_f16<<<dim3(2, GY), 256, SMEM_BYTES>>>(buf1, 512, wh_cw2, cb2,
                                               nullptr, 0, 256, MODE_DOT, cw3, clsbuf);
    // Fused head
    head_kernel<<<(MROWS + 127) / 128, 128>>>(outReg, clsbuf, cb3, qw1, qb1, qw2, qb2,
                                              outCls, outBox, MROWS);
}

// round 16
// speedup vs baseline: 1.4899x; 1.0132x over previous
#include <cuda_runtime.h>
#include <cuda_fp16.h>
#include <math.h>
#include <stdint.h>

// Problem constants
#define NIMG   32
#define HH     96
#define WW     96
#define LPIX   (HH*WW)              // 9216
#define MROWS  (NIMG*LPIX)          // 294912
#define NBINS  17
#define REGOUT (4*NBINS)            // 68
#define REGCH  64

// ---------------------------------------------------------------------------
// Scratch device globals (fp16 activations/weights)
// ---------------------------------------------------------------------------
__device__ __align__(16) __half g_xh[(size_t)MROWS * 256];    // fp16 x
__device__ __align__(16) __half g_buf1[(size_t)MROWS * 512];  // L1 out [cls h1 | reg h1]
__device__ __align__(16) __half g_buf2[(size_t)MROWS * 256];  // reg h2
__device__ float g_cls[(size_t)2 * MROWS];                    // cls dot partials [2][M]
// fp16 weights: [cw1(256) | rw1(256) | cw2(256) | rw2(256) | rw3(68)] x 256
__device__ __align__(16) __half g_wh[(size_t)(4 * 256 + 68) * 256];
__device__ float g_b512[512];                                 // concat(cb1, rb1)

// ---------------------------------------------------------------------------
// helpers
// ---------------------------------------------------------------------------
__device__ __forceinline__ uint32_t smem_u32(const void* p) {
    uint32_t a;
    asm("{ .reg .u64 t; cvta.to.shared.u64 t, %1; cvt.u32.u64 %0, t; }" : "=r"(a) : "l"(p));
    return a;
}
#define CP16(dst, gsrc, nbytes) \
    asm volatile("cp.async.cg.shared.global [%0], [%1], 16, %2;" \
                 :: "r"(dst), "l"(gsrc), "r"(nbytes))
#define CP_COMMIT() asm volatile("cp.async.commit_group;" ::: "memory")
#define CP_WAIT(n)  asm volatile("cp.async.wait_group %0;" :: "n"(n) : "memory")

// fp16 MMA m16n8k16, fp32 accumulate
#define MMA16(c, a, b)                                                       \
    asm volatile("mma.sync.aligned.m16n8k16.row.col.f32.f16.f16.f32 "        \
        "{%0,%1,%2,%3}, {%4,%5,%6,%7}, {%8,%9}, {%0,%1,%2,%3};"              \
        : "+f"((c)[0]), "+f"((c)[1]), "+f"((c)[2]), "+f"((c)[3])             \
        : "r"((a)[0]), "r"((a)[1]), "r"((a)[2]), "r"((a)[3]),                \
          "r"((b)[0]), "r"((b)[1]))

#define LDSM4(r0, r1, r2, r3, addr)                                          \
    asm volatile("ldmatrix.sync.aligned.m8n8.x4.shared.b16 {%0,%1,%2,%3}, [%4];" \
        : "=r"(r0), "=r"(r1), "=r"(r2), "=r"(r3) : "r"(addr))

#define LDSM2(r0, r1, addr)                                                  \
    asm volatile("ldmatrix.sync.aligned.m8n8.x2.shared.b16 {%0,%1}, [%2];"   \
        : "=r"(r0), "=r"(r1) : "r"(addr))

// BK = 64 fp16 columns per k-tile; row stride 144 B (128 data + 16 pad)
#define PADB 144
#define STAGE_B (128 * PADB)                 // 18432 B per operand per stage
#define NSTAGE 3
#define SMEM_BYTES (NSTAGE * STAGE_B * 2)    // 110592 -> 2 CTAs/SM
#define NKT 4                                // 256 / 64

#define MODE_STD 0   // bias + relu -> fp16 store
#define MODE_DOT 2   // bias + relu, dot with w3, partial-accumulate to dotOut

// ---------------------------------------------------------------------------
// fp16 mma GEMM (R9 config — mainloop unchanged): CTA 128x128, 256 thr,
// 8 warps (2x4) of 64x32 tiles, BK=64, 3-stage cp.async.
// ---------------------------------------------------------------------------
__global__ void __launch_bounds__(256, 2)
gemm_f16(const __half* __restrict__ A, int lda,
         const __half* __restrict__ W,
         const float* __restrict__ bias,
         void* __restrict__ Cout, int ldc, int Nout, int mode,
         const float* __restrict__ w3, float* __restrict__ dotOut)
{
    extern __shared__ __align__(16) char smraw[];
    const uint32_t smA = smem_u32(smraw);
    const uint32_t smB = smA + NSTAGE * STAGE_B;

    const int tid = threadIdx.x;
    const int bm = blockIdx.y * 128;
    const int bn = blockIdx.x * 128;
    const int warp = tid >> 5, lane = tid & 31;
    const int wm = warp & 1, wn = warp >> 1;
    const int lq = lane >> 2, lr = lane & 3;

    float acc[4][4][4];
#pragma unroll
    for (int i = 0; i < 4; i++)
#pragma unroll
        for (int j = 0; j < 4; j++)
#pragma unroll
            for (int q = 0; q < 4; q++) acc[i][j][q] = 0.f;

    const int lrow = tid >> 3;          // 0..31
    const int lseg = (tid & 7) * 8;     // halfs: 0,8,...,56

    const __half* aG = A + (size_t)(bm + lrow) * lda + lseg;
    const __half* bG = W + (size_t)(bn + lrow) * 256 + lseg;

    const uint32_t aFragOff = (uint32_t)((lane & 15) * PADB + ((lane >> 4) & 1) * 16)
                            + (uint32_t)(wm * 64 * PADB);
    const uint32_t bFragOff = (uint32_t)(((lane & 7) + ((lane >> 4) & 1) * 8) * PADB
                            + ((lane >> 3) & 1) * 16)
                            + (uint32_t)(wn * 32 * PADB);

#define ISSUE_TILE(buf, k0)                                                   \
    do {                                                                      \
        uint32_t dA = smA + (buf) * STAGE_B + lrow * PADB + (tid & 7) * 16;   \
        uint32_t dB = smB + (buf) * STAGE_B + lrow * PADB + (tid & 7) * 16;   \
        _Pragma("unroll")                                                     \
        for (int it = 0; it < 4; it++) {                                      \
            CP16(dA + it * 32 * PADB,                                         \
                 __cvta_generic_to_global(aG + (size_t)it * 32 * lda + (k0)), \
                 16);                                                         \
            int brow = bn + lrow + it * 32;                                   \
            CP16(dB + it * 32 * PADB,                                         \
                 __cvta_generic_to_global(bG + (size_t)it * 32 * 256 + (k0)), \
                 (brow < Nout) ? 16 : 0);                                     \
        }                                                                     \
        CP_COMMIT();                                                          \
    } while (0)

    ISSUE_TILE(0, 0);
    ISSUE_TILE(1, 64);

    for (int kt = 0; kt < NKT; kt++) {
        if (kt < NKT - 2) ISSUE_TILE((kt + 2) % NSTAGE, (kt + 2) * 64);
        else              CP_COMMIT();
        CP_WAIT(2);
        __syncthreads();

        const int buf = kt % NSTAGE;
        const uint32_t aBase = smA + (uint32_t)(buf * STAGE_B) + aFragOff;
        const uint32_t bBase = smB + (uint32_t)(buf * STAGE_B) + bFragOff;

#pragma unroll
        for (int kk = 0; kk < 4; kk++) {
            uint32_t a[4][4], b[4][2];
#pragma unroll
            for (int i = 0; i < 4; i++)
                LDSM4(a[i][0], a[i][1], a[i][2], a[i][3],
                      aBase + (uint32_t)(i * 16 * PADB + kk * 32));
#pragma unroll
            for (int jp = 0; jp < 2; jp++)
                LDSM4(b[2 * jp][0], b[2 * jp][1], b[2 * jp + 1][0], b[2 * jp + 1][1],
                      bBase + (uint32_t)(jp * 16 * PADB + kk * 32));
#pragma unroll
            for (int i = 0; i < 4; i++)
#pragma unroll
                for (int j = 0; j < 4; j++)
                    MMA16(acc[i][j], a[i], b[j]);
        }
        __syncthreads();
    }
#undef ISSUE_TILE

    // ---------------- Epilogue ----------------
    if (mode == MODE_DOT) {
        float* part = dotOut + (size_t)blockIdx.x * MROWS;
#pragma unroll
        for (int i = 0; i < 4; i++) {
            int r0 = bm + wm * 64 + i * 16 + lq;
            float s0 = 0.f, s1 = 0.f;
#pragma unroll
            for (int j = 0; j < 4; j++) {
                int col = bn + wn * 32 + j * 8 + 2 * lr;
                float b0 = __ldg(bias + col), b1 = __ldg(bias + col + 1);
                float w0 = __ldg(w3 + col), w1 = __ldg(w3 + col + 1);
                float c0 = fmaxf(acc[i][j][0] + b0, 0.f);
                float c1 = fmaxf(acc[i][j][1] + b1, 0.f);
                float c2 = fmaxf(acc[i][j][2] + b0, 0.f);
                float c3 = fmaxf(acc[i][j][3] + b1, 0.f);
                s0 = fmaf(c0, w0, fmaf(c1, w1, s0));
                s1 = fmaf(c2, w0, fmaf(c3, w1, s1));
            }
#pragma unroll
            for (int o = 1; o < 4; o <<= 1) {
                s0 += __shfl_xor_sync(0xffffffffu, s0, o);
                s1 += __shfl_xor_sync(0xffffffffu, s1, o);
            }
            if (lr == 0) {
                atomicAdd(part + r0, s0);
                atomicAdd(part + r0 + 8, s1);
            }
        }
        return;
    }

    // MODE_STD: bias + relu -> fp16
    {
        __half* C = (__half*)Cout;
#pragma unroll
        for (int i = 0; i < 4; i++) {
#pragma unroll
            for (int j = 0; j < 4; j++) {
                int row = bm + wm * 64 + i * 16 + lq;
                int col = bn + wn * 32 + j * 8 + 2 * lr;
                float b0 = __ldg(bias + col), b1 = __ldg(bias + col + 1);
                __half2 h01 = __floats2half2_rn(fmaxf(acc[i][j][0] + b0, 0.f),
                                                fmaxf(acc[i][j][1] + b1, 0.f));
                __half2 h23 = __floats2half2_rn(fmaxf(acc[i][j][2] + b0, 0.f),
                                                fmaxf(acc[i][j][3] + b1, 0.f));
                *(__half2*)(C + (size_t)row * ldc + col)       = h01;
                *(__half2*)(C + (size_t)(row + 8) * ldc + col) = h23;
            }
        }
    }
}

// ---------------------------------------------------------------------------
// reg layer-3 GEMM specialized for Nout=68: CTA tile 128x96, 8 warps of
// 64x24 (3 j-fragments). Same mainloop skeleton / stages; 25% fewer MMAs.
// grid = (1, M/128).
// ---------------------------------------------------------------------------
__global__ void __launch_bounds__(256, 2)
gemm_l3(const __half* __restrict__ A,         // buf2 [M,256]
        const __half* __restrict__ W,         // rw3 fp16 [68,256]
        const float* __restrict__ bias,       // rb3 [68]
        float* __restrict__ C)                // outReg [M,68]
{
    extern __shared__ __align__(16) char smraw[];
    const uint32_t smA = smem_u32(smraw);
    const uint32_t smB = smA + NSTAGE * STAGE_B;

    const int tid = threadIdx.x;
    const int bm = blockIdx.y * 128;
    const int warp = tid >> 5, lane = tid & 31;
    const int wm = warp & 1, wn = warp >> 1;       // wn: 24-col slice (0..3)
    const int lq = lane >> 2, lr = lane & 3;

    float acc[4][3][4];
#pragma unroll
    for (int i = 0; i < 4; i++)
#pragma unroll
        for (int j = 0; j < 3; j++)
#pragma unroll
            for (int q = 0; q < 4; q++) acc[i][j][q] = 0.f;

    const int lrow = tid >> 3;
    const int lseg = (tid & 7) * 8;

    const __half* aG = A + (size_t)(bm + lrow) * 256 + lseg;
    const __half* bG = W + (size_t)lrow * 256 + lseg;

    const uint32_t aFragOff = (uint32_t)((lane & 15) * PADB + ((lane >> 4) & 1) * 16)
                            + (uint32_t)(wm * 64 * PADB);
    // x4 pair (j0,j1): rows wn*24 .. wn*24+15
    const uint32_t bFragOff = (uint32_t)(((lane & 7) + ((lane >> 4) & 1) * 8) * PADB
                            + ((lane >> 3) & 1) * 16)
                            + (uint32_t)(wn * 24 * PADB);
    // x2 single (j2): rows wn*24+16 .. wn*24+23; addresses from lanes 0..15
    const uint32_t b2FragOff = (uint32_t)((lane & 7) * PADB
                             + ((lane >> 3) & 1) * 16)
                             + (uint32_t)((wn * 24 + 16) * PADB);

#define ISSUE_TILE(buf, k0)                                                   \
    do {                                                                      \
        uint32_t dA = smA + (buf) * STAGE_B + lrow * PADB + (tid & 7) * 16;   \
        uint32_t dB = smB + (buf) * STAGE_B + lrow * PADB + (tid & 7) * 16;   \
        _Pragma("unroll")                                                     \
        for (int it = 0; it < 4; it++) {                                      \
            CP16(dA + it * 32 * PADB,                                         \
                 __cvta_generic_to_global(aG + (size_t)it * 32 * 256 + (k0)), \
                 16);                                                         \
            int brow = lrow + it * 32;                                        \
            CP16(dB + it * 32 * PADB,                                         \
                 __cvta_generic_to_global(bG + (size_t)it * 32 * 256 + (k0)), \
                 (brow < 68) ? 16 : 0);                                       \
        }                                                                     \
        CP_COMMIT();                                                          \
    } while (0)

    ISSUE_TILE(0, 0);
    ISSUE_TILE(1, 64);

    for (int kt = 0; kt < NKT; kt++) {
        if (kt < NKT - 2) ISSUE_TILE((kt + 2) % NSTAGE, (kt + 2) * 64);
        else              CP_COMMIT();
        CP_WAIT(2);
        __syncthreads();

        const int buf = kt % NSTAGE;
        const uint32_t aBase = smA + (uint32_t)(buf * STAGE_B) + aFragOff;
        const uint32_t bBase = smB + (uint32_t)(buf * STAGE_B) + bFragOff;
        const uint32_t b2Base = smB + (uint32_t)(buf * STAGE_B) + b2FragOff;

#pragma unroll
        for (int kk = 0; kk < 4; kk++) {
            uint32_t a[4][4], b[3][2];
#pragma unroll
            for (int i = 0; i < 4; i++)
                LDSM4(a[i][0], a[i][1], a[i][2], a[i][3],
                      aBase + (uint32_t)(i * 16 * PADB + kk * 32));
            LDSM4(b[0][0], b[0][1], b[1][0], b[1][1],
                  bBase + (uint32_t)(kk * 32));
            LDSM2(b[2][0], b[2][1],
                  b2Base + (uint32_t)(kk * 32));
#pragma unroll
            for (int i = 0; i < 4; i++)
#pragma unroll
                for (int j = 0; j < 3; j++)
                    MMA16(acc[i][j], a[i], b[j]);
        }
        __syncthreads();
    }
#undef ISSUE_TILE

    // Epilogue: bias, fp32 store, col < 68 guard
#pragma unroll
    for (int i = 0; i < 4; i++) {
#pragma unroll
        for (int j = 0; j < 3; j++) {
            int row = bm + wm * 64 + i * 16 + lq;
            int col = wn * 24 + j * 8 + 2 * lr;
            if (col >= 68) continue;
            float b0 = __ldg(bias + col), b1 = __ldg(bias + col + 1);
            *(float2*)(C + (size_t)row * 68 + col) =
                make_float2(acc[i][j][0] + b0, acc[i][j][1] + b1);
            *(float2*)(C + (size_t)(row + 8) * 68 + col) =
                make_float2(acc[i][j][2] + b0, acc[i][j][3] + b1);
        }
    }
}

// ---------------------------------------------------------------------------
// x -> fp16 conversion (float4 -> 4 halfs)
// ---------------------------------------------------------------------------
__global__ void __launch_bounds__(256)
xcvt_kernel(const float4* __restrict__ in, __half* __restrict__ out, long n4)
{
    long i = (long)blockIdx.x * blockDim.x + threadIdx.x;
    if (i >= n4) return;
    float4 v = in[i];
    union { __half2 h2[2]; uint2 u; } pk;
    pk.h2[0] = __floats2half2_rn(v.x, v.y);
    pk.h2[1] = __floats2half2_rn(v.z, v.w);
    *(uint2*)(out + i * 4) = pk.u;
}

// ---------------------------------------------------------------------------
// prep1: L1 weights (cw1 | rw1) -> fp16 wh_l1   (32768 float4s)
// ---------------------------------------------------------------------------
__global__ void __launch_bounds__(256)
prep1_kernel(const float4* __restrict__ cw1, const float4* __restrict__ rw1,
             __half* __restrict__ wh_l1)
{
    int i = blockIdx.x * blockDim.x + threadIdx.x;
    if (i >= 32768) return;
    float4 v = (i < 16384) ? cw1[i] : rw1[i - 16384];
    union { __half2 h2[2]; uint2 u; } pk;
    pk.h2[0] = __floats2half2_rn(v.x, v.y);
    pk.h2[1] = __floats2half2_rn(v.z, v.w);
    *(uint2*)(wh_l1 + (size_t)i * 4) = pk.u;
}

// ---------------------------------------------------------------------------
// prep2: cw2/rw2/rw3 -> fp16, concat biases, zero cls partial buffers
// ---------------------------------------------------------------------------
__global__ void __launch_bounds__(256)
prep2_kernel(const float4* __restrict__ cw2, const float4* __restrict__ rw2,
             const float4* __restrict__ rw3,
             const float4* __restrict__ cb1, const float4* __restrict__ rb1,
             __half* __restrict__ wh_cw2, __half* __restrict__ wh_rw2,
             __half* __restrict__ wh_rw3, float4* __restrict__ b512,
             float4* __restrict__ clszero)
{
    int i = blockIdx.x * blockDim.x + threadIdx.x;
    union { __half2 h2[2]; uint2 u; } pk;
    if (i < 16384) {
        float4 v = cw2[i];
        pk.h2[0] = __floats2half2_rn(v.x, v.y);
        pk.h2[1] = __floats2half2_rn(v.z, v.w);
        *(uint2*)(wh_cw2 + (size_t)i * 4) = pk.u;
    } else if (i < 32768) {
        float4 v = rw2[i - 16384];
        pk.h2[0] = __floats2half2_rn(v.x, v.y);
        pk.h2[1] = __floats2half2_rn(v.z, v.w);
        *(uint2*)(wh_rw2 + (size_t)(i - 16384) * 4) = pk.u;
    } else if (i < 37120) {
        float4 v = rw3[i - 32768];
        pk.h2[0] = __floats2half2_rn(v.x, v.y);
        pk.h2[1] = __floats2half2_rn(v.z, v.w);
        *(uint2*)(wh_rw3 + (size_t)(i - 32768) * 4) = pk.u;
    } else if (i < 37248) {
        int k = i - 37120;
        b512[k] = (k < 64) ? cb1[k] : rb1[k - 64];
    } else if (i < 37248 + 147456) {
        clszero[i - 37248] = make_float4(0.f, 0.f, 0.f, 0.f);
    }
}

// ---------------------------------------------------------------------------
// Head: softmax-17 x4, top4+mean, quality MLP, sigmoid(cls)*q, integral box.
// cls logit = clsPart[0][p] + clsPart[1][p] + cb3.
// ---------------------------------------------------------------------------
__global__ void __launch_bounds__(128)
head_kernel(const float* __restrict__ reg, const float* __restrict__ clsl,
            const float* __restrict__ cb3,
            const float* __restrict__ qw1, const float* __restrict__ qb1,
            const float* __restrict__ qw2, const float* __restrict__ qb2,
            float* __restrict__ outCls, float* __restrict__ outBox, int M)
{
    __shared__ float sw1[REGCH * 20];
    __shared__ float sb1[REGCH];
    __shared__ float sw2[REGCH];
    __shared__ float sb2;
    for (int i = threadIdx.x; i < REGCH * 20; i += blockDim.x) sw1[i] = qw1[i];
    for (int i = threadIdx.x; i < REGCH; i += blockDim.x) {
        sb1[i] = qb1[i];
        sw2[i] = qw2[i];
    }
    if (threadIdx.x == 0) sb2 = qb2[0];
    __syncthreads();

    int p = blockIdx.x * blockDim.x + threadIdx.x;
    if (p >= M) return;

    const float* rp = reg + (size_t)p * REGOUT;
    float stat[20], box[4];
#pragma unroll
    for (int s = 0; s < 4; s++) {
        float v[NBINS];
        float mx = -1e30f;
#pragma unroll
        for (int i = 0; i < NBINS; i++) { v[i] = rp[s * NBINS + i]; mx = fmaxf(mx, v[i]); }
        float sum = 0.f;
#pragma unroll
        for (int i = 0; i < NBINS; i++) { v[i] = expf(v[i] - mx); sum += v[i]; }
        float inv = 1.f / sum, integ = 0.f;
#pragma unroll
        for (int i = 0; i < NBINS; i++) { v[i] *= inv; integ += v[i] * (float)i; }
        box[s] = integ * (1.f / 16.f);
        float mean4 = 0.f;
        for (int k = 0; k < 4; k++) {
            float best = -1.f;
            int bi = 0;
#pragma unroll
            for (int i = 0; i < NBINS; i++)
                if (v[i] > best) { best = v[i]; bi = i; }
            stat[s * 5 + k] = best;
            mean4 += best;
            v[bi] = -2.f;
        }
        stat[s * 5 + 4] = mean4 * 0.25f;
    }
    float q = sb2;
    for (int o = 0; o < REGCH; o++) {
        float h = sb1[o];
#pragma unroll
        for (int c = 0; c < 20; c++) h = fmaf(sw1[o * 20 + c], stat[c], h);
        q = fmaf(sw2[o], fmaxf(h, 0.f), q);
    }
    q = 1.f / (1.f + expf(-q));
    float logit = clsl[p] + clsl[p + MROWS] + __ldg(cb3);
    float cl = 1.f / (1.f + expf(-logit));
    outCls[p] = cl * q;
    *(float4*)&outBox[(size_t)p * 4] = make_float4(box[0], box[1], box[2], box[3]);
}

// ---------------------------------------------------------------------------
// Launcher (single stream)
// ---------------------------------------------------------------------------
extern "C" void kernel_launch(void* const* d_in, const int* in_sizes, int n_in,
                              void* d_out, int out_size)
{
    const float* x   = (const float*)d_in[0];
    const float* cw1 = (const float*)d_in[1];
    const float* cb1 = (const float*)d_in[2];
    const float* cw2 = (const float*)d_in[3];
    const float* cb2 = (const float*)d_in[4];
    const float* cw3 = (const float*)d_in[5];
    const float* cb3 = (const float*)d_in[6];
    const float* rw1 = (const float*)d_in[7];
    const float* rb1 = (const float*)d_in[8];
    const float* rw2 = (const float*)d_in[9];
    const float* rb2 = (const float*)d_in[10];
    const float* rw3 = (const float*)d_in[11];
    const float* rb3 = (const float*)d_in[12];
    const float* qw1 = (const float*)d_in[13];
    const float* qb1 = (const float*)d_in[14];
    const float* qw2 = (const float*)d_in[15];
    const float* qb2 = (const float*)d_in[16];

    float* out = (float*)d_out;
    float* outCls = out;
    float* outBox = out + (size_t)MROWS;
    float* outReg = out + (size_t)MROWS * 5;

    __half *xh, *buf1, *buf2, *wh;
    float *clsbuf, *b512;
    cudaGetSymbolAddress((void**)&xh, g_xh);
    cudaGetSymbolAddress((void**)&buf1, g_buf1);
    cudaGetSymbolAddress((void**)&buf2, g_buf2);
    cudaGetSymbolAddress((void**)&clsbuf, g_cls);
    cudaGetSymbolAddress((void**)&wh, g_wh);
    cudaGetSymbolAddress((void**)&b512, g_b512);

    __half* wh_l1  = wh;                          // cw1 rows 0..255, rw1 rows 256..511
    __half* wh_cw2 = wh + (size_t)512 * 256;
    __half* wh_rw2 = wh + (size_t)768 * 256;
    __half* wh_rw3 = wh + (size_t)1024 * 256;

    cudaFuncSetAttribute(gemm_f16, cudaFuncAttributeMaxDynamicSharedMemorySize, SMEM_BYTES);
    cudaFuncSetAttribute(gemm_l3, cudaFuncAttributeMaxDynamicSharedMemorySize, SMEM_BYTES);

    // prep
    prep1_kernel<<<128, 256>>>((const float4*)cw1, (const float4*)rw1, wh_l1);
    prep2_kernel<<<722, 256>>>((const float4*)cw2, (const float4*)rw2, (const float4*)rw3,
                               (const float4*)cb1, (const float4*)rb1,
                               wh_cw2, wh_rw2, wh_rw3,
                               (float4*)b512, (float4*)clsbuf);
    xcvt_kernel<<<(MROWS * 64 + 255) / 256, 256>>>((const float4*)x, xh, (long)MROWS * 64);

    const int GY = MROWS / 128;  // 2304

    // Fused layer-1: x(fp16) -> [cls h1 | reg h1] fp16
    gemm_f16<<<dim3(4, GY), 256, SMEM_BYTES>>>(xh, 256, wh_l1, b512,
                                               buf1, 512, 512, MODE_STD, nullptr, nullptr);
    // reg layer-2
    gemm_f16<<<dim3(2, GY), 256, SMEM_BYTES>>>(buf1 + 256, 512, wh_rw2, rb2,
                                               buf2, 256, 256, MODE_STD, nullptr, nullptr);
    // reg layer-3 (Nout=68, narrow 128x96 tile) -> reg_pred output
    gemm_l3<<<dim3(1, GY), 256, SMEM_BYTES>>>(buf2, wh_rw3, rb3, outReg);
    // cls layer-2 + fused dot with cw3 -> clsbuf partials
    gemm_f16<<<dim3(2, GY), 256, SMEM_BYTES>>>(buf1, 512, wh_cw2, cb2,
                                               nullptr, 0, 256, MODE_DOT, cw3, clsbuf);
    // Fused head
    head_kernel<<<(MROWS + 127) / 128, 128>>>(outReg, clsbuf, cb3, qw1, qb1, qw2, qb2,
                                              outCls, outBox, MROWS);
}